// round 5
// baseline (speedup 1.0000x reference)
#include <cuda_runtime.h>
#include <cstdint>
#include <cstddef>

// Problem constants
#define LNUM 3
#define HDIM 128
#define NHEADS 8
#define HD 16
#define FF 512
#define BSZ 32
#define NN 512
#define ROWS (BSZ*NN)          // 16384
#define NUM_BINS 50
#define KVS 20                 // K/V smem row stride in floats (80B = odd multiple of 16B)

// -------------------- scratch (device globals; no allocation) --------------------
__device__ float g_t0[ROWS*HDIM];
__device__ float g_q [ROWS*HDIM];
__device__ float g_k [ROWS*HDIM];
__device__ float g_v [ROWS*HDIM];
__device__ float g_a [ROWS*HDIM];
__device__ float g_u [ROWS*2*FF];

// -------------------- LayerNorm: one warp per 128-elem row --------------------
__global__ void ln_kernel(const float* __restrict__ x, const float* __restrict__ g,
                          const float* __restrict__ b, float* __restrict__ y)
{
    int warp = threadIdx.x >> 5, lane = threadIdx.x & 31;
    int row  = blockIdx.x * 8 + warp;
    const float4* x4 = (const float4*)(x + (size_t)row * HDIM);
    float4 v = x4[lane];
    float s  = v.x + v.y + v.z + v.w;
    float sq = v.x*v.x + v.y*v.y + v.z*v.z + v.w*v.w;
    #pragma unroll
    for (int o = 16; o > 0; o >>= 1) {
        s  += __shfl_xor_sync(0xffffffffu, s,  o);
        sq += __shfl_xor_sync(0xffffffffu, sq, o);
    }
    float mu  = s * (1.0f/128.0f);
    float var = sq * (1.0f/128.0f) - mu*mu;
    float rs  = rsqrtf(var + 1e-5f);
    float4 gg = ((const float4*)g)[lane];
    float4 bb = ((const float4*)b)[lane];
    float4 o;
    o.x = (v.x - mu) * rs * gg.x + bb.x;
    o.y = (v.y - mu) * rs * gg.y + bb.y;
    o.z = (v.z - mu) * rs * gg.z + bb.z;
    o.w = (v.w - mu) * rs * gg.w + bb.w;
    ((float4*)(y + (size_t)row * HDIM))[lane] = o;
}

// -------------------- deep-K tiled fp32 GEMM: C = [C +] act(A)[M,K] @ W[K,N] + bias --------------------
// Tile: 64x64 output, K processed in chunks of 128 with ONE sync pair per chunk.
// GLU=true: A row has stride lda=2*FF; element(k) = A[k] * sigmoid(A[k+FF]).
#define AS_STRIDE 132
template<bool ADD, bool GLU>
__global__ __launch_bounds__(256)
void gemm_k(const float* __restrict__ A, const float* __restrict__ W,
            const float* __restrict__ bias, float* __restrict__ C,
            int N, int K, int lda)
{
    extern __shared__ float sh[];
    float* As = sh;                    // [64][132]
    float* Ws = sh + 64*AS_STRIDE;     // [128][64]
    int tid = threadIdx.x;
    int tx = tid & 15, ty = tid >> 4;
    int m0 = blockIdx.y * 64, n0 = blockIdx.x * 64;

    float acc[4][4];
    #pragma unroll
    for (int i = 0; i < 4; i++)
        #pragma unroll
        for (int j = 0; j < 4; j++) acc[i][j] = 0.0f;

    for (int k0 = 0; k0 < K; k0 += 128) {
        // load A tile 64 x 128 (each warp fills one row per iteration; coalesced 512B)
        #pragma unroll
        for (int it = 0; it < 8; it++) {
            int idx = tid + it*256;            // 0..2047
            int m = idx >> 5, c4 = idx & 31;
            const float* arow = A + (size_t)(m0 + m) * lda + k0;
            float4 av = *(const float4*)(arow + c4*4);
            if (GLU) {
                float4 cv = *(const float4*)(arow + FF + c4*4);
                av.x = av.x / (1.0f + __expf(-cv.x));
                av.y = av.y / (1.0f + __expf(-cv.y));
                av.z = av.z / (1.0f + __expf(-cv.z));
                av.w = av.w / (1.0f + __expf(-cv.w));
            }
            *(float4*)&As[m*AS_STRIDE + c4*4] = av;
        }
        // load W tile 128 x 64
        #pragma unroll
        for (int it = 0; it < 8; it++) {
            int idx = tid + it*256;
            int k = idx >> 4, c4 = idx & 15;
            float4 wv = *(const float4*)(W + (size_t)(k0 + k) * N + n0 + c4*4);
            *(float4*)&Ws[k*64 + c4*4] = wv;
        }
        __syncthreads();

        #pragma unroll 8
        for (int k = 0; k < 128; k++) {
            float a0 = As[(ty*4+0)*AS_STRIDE + k];
            float a1 = As[(ty*4+1)*AS_STRIDE + k];
            float a2 = As[(ty*4+2)*AS_STRIDE + k];
            float a3 = As[(ty*4+3)*AS_STRIDE + k];
            float4 bv = *(float4*)&Ws[k*64 + tx*4];
            acc[0][0] = fmaf(a0, bv.x, acc[0][0]); acc[0][1] = fmaf(a0, bv.y, acc[0][1]);
            acc[0][2] = fmaf(a0, bv.z, acc[0][2]); acc[0][3] = fmaf(a0, bv.w, acc[0][3]);
            acc[1][0] = fmaf(a1, bv.x, acc[1][0]); acc[1][1] = fmaf(a1, bv.y, acc[1][1]);
            acc[1][2] = fmaf(a1, bv.z, acc[1][2]); acc[1][3] = fmaf(a1, bv.w, acc[1][3]);
            acc[2][0] = fmaf(a2, bv.x, acc[2][0]); acc[2][1] = fmaf(a2, bv.y, acc[2][1]);
            acc[2][2] = fmaf(a2, bv.z, acc[2][2]); acc[2][3] = fmaf(a2, bv.w, acc[2][3]);
            acc[3][0] = fmaf(a3, bv.x, acc[3][0]); acc[3][1] = fmaf(a3, bv.y, acc[3][1]);
            acc[3][2] = fmaf(a3, bv.z, acc[3][2]); acc[3][3] = fmaf(a3, bv.w, acc[3][3]);
        }
        __syncthreads();
    }

    float4 bvec = *(const float4*)(bias + n0 + tx*4);
    float bs[4] = {bvec.x, bvec.y, bvec.z, bvec.w};
    #pragma unroll
    for (int i = 0; i < 4; i++) {
        size_t off = (size_t)(m0 + ty*4 + i) * N + n0 + tx*4;
        float4 o;
        o.x = acc[i][0] + bs[0];
        o.y = acc[i][1] + bs[1];
        o.z = acc[i][2] + bs[2];
        o.w = acc[i][3] + bs[3];
        if (ADD) {
            float4 r = *(const float4*)(C + off);
            o.x += r.x; o.y += r.y; o.z += r.z; o.w += r.w;
        }
        *(float4*)(C + off) = o;
    }
}
#define GEMM_SMEM ((64*AS_STRIDE + 128*64) * (int)sizeof(float))

// -------------------- fused attention: warp per query row, full K/V for (b,h) in smem --------------------
// K/V rows padded to 20 floats (80B): odd multiple of 16B => LDS.128 conflict-free across lanes.
__global__ __launch_bounds__(512)
void attn_kernel(const float* __restrict__ Q, const float* __restrict__ Kt,
                 const float* __restrict__ V, const float* __restrict__ dist,
                 const unsigned int* __restrict__ mask,   // 4-byte elements; nonzero = masked
                 const float* __restrict__ demb,   // [50,8] for this layer
                 const float* __restrict__ abias,  // [8]    for this layer
                 float* __restrict__ out)
{
    extern __shared__ float sm[];
    float* Ksh = sm;                 // 512*20
    float* Vsh = Ksh + NN*KVS;       // 512*20
    float* mb  = Vsh + NN*KVS;       // 512
    float* de  = mb + NN;            // 64
    float4* K4 = (float4*)Ksh;
    float4* V4 = (float4*)Vsh;

    int b = blockIdx.x >> 3, h = blockIdx.x & 7;
    int tid = threadIdx.x;

    // cooperative load of K,V head slice [512,16] into padded smem (float4 granularity)
    for (int idx = tid; idx < NN*4; idx += 512) {
        int r = idx >> 2, c = idx & 3;
        size_t goff = ((size_t)b*NN + r) * HDIM + h*HD + c*4;
        K4[r*5 + c] = *(const float4*)(Kt + goff);
        V4[r*5 + c] = *(const float4*)(V  + goff);
    }
    if (tid < NN)  mb[tid] = (mask[(size_t)b*NN + tid] != 0u) ? -1e9f : 0.0f;
    if (tid < NUM_BINS) de[tid] = demb[tid*NHEADS + h];
    float ab = abias[h];
    __syncthreads();

    int warp = tid >> 5, lane = tid & 31;
    int qbase = blockIdx.y * 64 + warp * 4;

    for (int r = 0; r < 4; r++) {
        int q = qbase + r;
        const float4* qp = (const float4*)(Q + ((size_t)b*NN + q) * HDIM + h*HD);
        float4 q0 = qp[0], q1 = qp[1], q2 = qp[2], q3 = qp[3];

        const float* drow = dist + ((size_t)b*NN + q) * NN;
        float sc[16];
        float mx = -3.4e38f;
        #pragma unroll
        for (int kk = 0; kk < 16; kk++) {
            int k = kk*32 + lane;
            float dv = drow[k];                       // coalesced across lanes
            int bin = (int)(dv * 10.0f);
            bin = bin < 0 ? 0 : (bin > NUM_BINS-1 ? NUM_BINS-1 : bin);
            float4 ka = K4[k*5+0], kb = K4[k*5+1], kc = K4[k*5+2], kd = K4[k*5+3];
            float dot;
            dot = q0.x*ka.x;
            dot = fmaf(q0.y, ka.y, dot); dot = fmaf(q0.z, ka.z, dot); dot = fmaf(q0.w, ka.w, dot);
            dot = fmaf(q1.x, kb.x, dot); dot = fmaf(q1.y, kb.y, dot);
            dot = fmaf(q1.z, kb.z, dot); dot = fmaf(q1.w, kb.w, dot);
            dot = fmaf(q2.x, kc.x, dot); dot = fmaf(q2.y, kc.y, dot);
            dot = fmaf(q2.z, kc.z, dot); dot = fmaf(q2.w, kc.w, dot);
            dot = fmaf(q3.x, kd.x, dot); dot = fmaf(q3.y, kd.y, dot);
            dot = fmaf(q3.z, kd.z, dot); dot = fmaf(q3.w, kd.w, dot);
            float s = dot * 0.25f + de[bin] + ab + mb[k];
            sc[kk] = s;
            mx = fmaxf(mx, s);
        }
        #pragma unroll
        for (int o = 16; o > 0; o >>= 1)
            mx = fmaxf(mx, __shfl_xor_sync(0xffffffffu, mx, o));

        float ssum = 0.0f;
        float4 ac0 = {0,0,0,0}, ac1 = {0,0,0,0}, ac2 = {0,0,0,0}, ac3 = {0,0,0,0};
        #pragma unroll
        for (int kk = 0; kk < 16; kk++) {
            int k = kk*32 + lane;
            float p = __expf(fmaxf(sc[kk] - mx, -80.0f));
            ssum += p;
            float4 va = V4[k*5+0], vb = V4[k*5+1], vc = V4[k*5+2], vd = V4[k*5+3];
            ac0.x = fmaf(p, va.x, ac0.x); ac0.y = fmaf(p, va.y, ac0.y);
            ac0.z = fmaf(p, va.z, ac0.z); ac0.w = fmaf(p, va.w, ac0.w);
            ac1.x = fmaf(p, vb.x, ac1.x); ac1.y = fmaf(p, vb.y, ac1.y);
            ac1.z = fmaf(p, vb.z, ac1.z); ac1.w = fmaf(p, vb.w, ac1.w);
            ac2.x = fmaf(p, vc.x, ac2.x); ac2.y = fmaf(p, vc.y, ac2.y);
            ac2.z = fmaf(p, vc.z, ac2.z); ac2.w = fmaf(p, vc.w, ac2.w);
            ac3.x = fmaf(p, vd.x, ac3.x); ac3.y = fmaf(p, vd.y, ac3.y);
            ac3.z = fmaf(p, vd.z, ac3.z); ac3.w = fmaf(p, vd.w, ac3.w);
        }
        float accv[16] = {ac0.x,ac0.y,ac0.z,ac0.w, ac1.x,ac1.y,ac1.z,ac1.w,
                          ac2.x,ac2.y,ac2.z,ac2.w, ac3.x,ac3.y,ac3.z,ac3.w};
        #pragma unroll
        for (int o = 16; o > 0; o >>= 1) {
            ssum += __shfl_xor_sync(0xffffffffu, ssum, o);
            #pragma unroll
            for (int d = 0; d < HD; d++)
                accv[d] += __shfl_xor_sync(0xffffffffu, accv[d], o);
        }
        if (lane == 0) {
            float inv = 1.0f / ssum;
            float4* o4 = (float4*)(out + ((size_t)b*NN + q) * HDIM + h*HD);
            o4[0] = make_float4(accv[0]*inv,  accv[1]*inv,  accv[2]*inv,  accv[3]*inv);
            o4[1] = make_float4(accv[4]*inv,  accv[5]*inv,  accv[6]*inv,  accv[7]*inv);
            o4[2] = make_float4(accv[8]*inv,  accv[9]*inv,  accv[10]*inv, accv[11]*inv);
            o4[3] = make_float4(accv[12]*inv, accv[13]*inv, accv[14]*inv, accv[15]*inv);
        }
    }
}
#define ATTN_SMEM ((2*NN*KVS + NN + 64) * (int)sizeof(float))

// -------------------- launch --------------------
extern "C" void kernel_launch(void* const* d_in, const int* in_sizes, int n_in,
                              void* d_out, int out_size)
{
    const float*        x    = (const float*)d_in[0];
    const float*        dist = (const float*)d_in[1];
    const unsigned int* mask = (const unsigned int*)d_in[2];  // bool widened to 4-byte dtype
    const float* Wq  = (const float*)d_in[3];
    const float* bq  = (const float*)d_in[4];
    const float* Wk  = (const float*)d_in[5];
    const float* bk  = (const float*)d_in[6];
    const float* Wv  = (const float*)d_in[7];
    const float* bv  = (const float*)d_in[8];
    const float* Wo  = (const float*)d_in[9];
    const float* bo  = (const float*)d_in[10];
    const float* demb  = (const float*)d_in[11];
    const float* abias = (const float*)d_in[12];
    const float* g1  = (const float*)d_in[13];
    const float* b1  = (const float*)d_in[14];
    const float* g2  = (const float*)d_in[15];
    const float* b2  = (const float*)d_in[16];
    const float* Wf1 = (const float*)d_in[17];
    const float* bf1 = (const float*)d_in[18];
    const float* Wf2 = (const float*)d_in[19];
    const float* bf2 = (const float*)d_in[20];
    float* h = (float*)d_out;

    float *t0, *q, *k, *v, *a, *u;
    cudaGetSymbolAddress((void**)&t0, g_t0);
    cudaGetSymbolAddress((void**)&q,  g_q);
    cudaGetSymbolAddress((void**)&k,  g_k);
    cudaGetSymbolAddress((void**)&v,  g_v);
    cudaGetSymbolAddress((void**)&a,  g_a);
    cudaGetSymbolAddress((void**)&u,  g_u);

    cudaFuncSetAttribute(attn_kernel, cudaFuncAttributeMaxDynamicSharedMemorySize, ATTN_SMEM);
    cudaFuncSetAttribute(gemm_k<false,false>, cudaFuncAttributeMaxDynamicSharedMemorySize, GEMM_SMEM);
    cudaFuncSetAttribute(gemm_k<true, false>, cudaFuncAttributeMaxDynamicSharedMemorySize, GEMM_SMEM);
    cudaFuncSetAttribute(gemm_k<true, true >, cudaFuncAttributeMaxDynamicSharedMemorySize, GEMM_SMEM);

    cudaMemcpyAsync(h, x, sizeof(float)*(size_t)ROWS*HDIM, cudaMemcpyDeviceToDevice, 0);

    for (int l = 0; l < LNUM; l++) {
        ln_kernel<<<ROWS/8, 256>>>(h, g1 + l*HDIM, b1 + l*HDIM, t0);

        gemm_k<false,false><<<dim3(HDIM/64, ROWS/64), 256, GEMM_SMEM>>>(t0, Wq + (size_t)l*HDIM*HDIM, bq + l*HDIM, q, HDIM, HDIM, HDIM);
        gemm_k<false,false><<<dim3(HDIM/64, ROWS/64), 256, GEMM_SMEM>>>(t0, Wk + (size_t)l*HDIM*HDIM, bk + l*HDIM, k, HDIM, HDIM, HDIM);
        gemm_k<false,false><<<dim3(HDIM/64, ROWS/64), 256, GEMM_SMEM>>>(t0, Wv + (size_t)l*HDIM*HDIM, bv + l*HDIM, v, HDIM, HDIM, HDIM);

        attn_kernel<<<dim3(BSZ*NHEADS, NN/64), 512, ATTN_SMEM>>>(q, k, v, dist, mask,
                                                                 demb + l*NUM_BINS*NHEADS,
                                                                 abias + l*NHEADS, a);

        gemm_k<true,false><<<dim3(HDIM/64, ROWS/64), 256, GEMM_SMEM>>>(a, Wo + (size_t)l*HDIM*HDIM, bo + l*HDIM, h, HDIM, HDIM, HDIM);

        ln_kernel<<<ROWS/8, 256>>>(h, g2 + l*HDIM, b2 + l*HDIM, t0);

        // FF1: t0[16384,128] @ Wf1[128,1024] -> u
        gemm_k<false,false><<<dim3((2*FF)/64, ROWS/64), 256, GEMM_SMEM>>>(t0, Wf1 + (size_t)l*HDIM*2*FF, bf1 + l*2*FF, u, 2*FF, HDIM, HDIM);

        // FF2 with fused GLU on the A-tile load: h += glu(u) @ Wf2 + bf2
        gemm_k<true,true><<<dim3(HDIM/64, ROWS/64), 256, GEMM_SMEM>>>(u, Wf2 + (size_t)l*FF*HDIM, bf2 + l*HDIM, h, HDIM, FF, 2*FF);
    }
}

// round 8
// speedup vs baseline: 2.2551x; 2.2551x over previous
#include <cuda_runtime.h>
#include <cstdint>
#include <cstddef>

// Problem constants
#define LNUM 3
#define HDIM 128
#define NHEADS 8
#define HD 16
#define FF 512
#define BSZ 32
#define NN 512
#define ROWS (BSZ*NN)          // 16384
#define NUM_BINS 50
#define KS 17                  // padded smem stride for attention K/V tiles (R3-proven)

// -------------------- scratch (device globals; no allocation) --------------------
__device__ float g_t0[ROWS*HDIM];
__device__ float g_q [ROWS*HDIM];
__device__ float g_k [ROWS*HDIM];
__device__ float g_v [ROWS*HDIM];
__device__ float g_a [ROWS*HDIM];
__device__ float g_u [ROWS*2*FF];
__device__ float g_g [ROWS*FF];

// -------------------- LayerNorm: one warp per 128-elem row (R3) --------------------
__global__ void ln_kernel(const float* __restrict__ x, const float* __restrict__ g,
                          const float* __restrict__ b, float* __restrict__ y)
{
    int warp = threadIdx.x >> 5, lane = threadIdx.x & 31;
    int row  = blockIdx.x * 8 + warp;
    const float4* x4 = (const float4*)(x + (size_t)row * HDIM);
    float4 v = x4[lane];
    float s  = v.x + v.y + v.z + v.w;
    float sq = v.x*v.x + v.y*v.y + v.z*v.z + v.w*v.w;
    #pragma unroll
    for (int o = 16; o > 0; o >>= 1) {
        s  += __shfl_xor_sync(0xffffffffu, s,  o);
        sq += __shfl_xor_sync(0xffffffffu, sq, o);
    }
    float mu  = s * (1.0f/128.0f);
    float var = sq * (1.0f/128.0f) - mu*mu;
    float rs  = rsqrtf(var + 1e-5f);
    float4 gg = ((const float4*)g)[lane];
    float4 bb = ((const float4*)b)[lane];
    float4 o;
    o.x = (v.x - mu) * rs * gg.x + bb.x;
    o.y = (v.y - mu) * rs * gg.y + bb.y;
    o.z = (v.z - mu) * rs * gg.z + bb.z;
    o.w = (v.w - mu) * rs * gg.w + bb.w;
    ((float4*)(y + (size_t)row * HDIM))[lane] = o;
}

// -------------------- 128x128-tile fp32 GEMM, 8x8 microtile --------------------
// Per k-step per thread: 8 dual-broadcast scalar LDS (A, stride 33) +
// 2 conflict-free LDS.128 (B, split columns tx*4 / 64+tx*4) + 64 FMA.
// Static smem: As 128*33*4 + Bs 32*132*4 = 33792 B. 256 threads.
#define ASTR 33
#define BSTR 132
template<bool ADD>
__device__ __forceinline__
void gemm128_body(const float* __restrict__ A, const float* __restrict__ W,
                  const float* __restrict__ bias, float* __restrict__ C,
                  int N, int K, int lda, int m0, int n0)
{
    __shared__ float As[128*ASTR];
    __shared__ float Bs[32*BSTR];
    int tid = threadIdx.x;
    int tx = tid & 15, ty = tid >> 4;

    float acc[8][8];
    #pragma unroll
    for (int i = 0; i < 8; i++)
        #pragma unroll
        for (int j = 0; j < 8; j++) acc[i][j] = 0.0f;

    for (int k0 = 0; k0 < K; k0 += 32) {
        // A tile: 128 rows x 32 k (1024 float4); scalar stores into odd-stride array
        #pragma unroll
        for (int it = 0; it < 4; it++) {
            int idx = tid + it*256;
            int row = idx >> 3, c4 = idx & 7;
            float4 av = *(const float4*)(A + (size_t)(m0 + row) * lda + k0 + c4*4);
            int base = row*ASTR + c4*4;
            As[base+0] = av.x; As[base+1] = av.y; As[base+2] = av.z; As[base+3] = av.w;
        }
        // B tile: 32 k-rows x 128 cols (1024 float4)
        #pragma unroll
        for (int it = 0; it < 4; it++) {
            int idx = tid + it*256;
            int kk = idx >> 5, c4 = idx & 31;
            *(float4*)&Bs[kk*BSTR + c4*4] =
                *(const float4*)(W + (size_t)(k0 + kk) * N + n0 + c4*4);
        }
        __syncthreads();

        #pragma unroll 4
        for (int k = 0; k < 32; k++) {
            float4 b0 = *(float4*)&Bs[k*BSTR + tx*4];
            float4 b1 = *(float4*)&Bs[k*BSTR + 64 + tx*4];
            #pragma unroll
            for (int i = 0; i < 8; i++) {
                float a = As[(ty*8 + i)*ASTR + k];
                acc[i][0] = fmaf(a, b0.x, acc[i][0]);
                acc[i][1] = fmaf(a, b0.y, acc[i][1]);
                acc[i][2] = fmaf(a, b0.z, acc[i][2]);
                acc[i][3] = fmaf(a, b0.w, acc[i][3]);
                acc[i][4] = fmaf(a, b1.x, acc[i][4]);
                acc[i][5] = fmaf(a, b1.y, acc[i][5]);
                acc[i][6] = fmaf(a, b1.z, acc[i][6]);
                acc[i][7] = fmaf(a, b1.w, acc[i][7]);
            }
        }
        __syncthreads();
    }

    float4 bv0 = *(const float4*)(bias + n0 + tx*4);
    float4 bv1 = *(const float4*)(bias + n0 + 64 + tx*4);
    #pragma unroll
    for (int i = 0; i < 8; i++) {
        size_t off0 = (size_t)(m0 + ty*8 + i) * N + n0 + tx*4;
        size_t off1 = off0 + 64;
        float4 o0, o1;
        o0.x = acc[i][0] + bv0.x; o0.y = acc[i][1] + bv0.y;
        o0.z = acc[i][2] + bv0.z; o0.w = acc[i][3] + bv0.w;
        o1.x = acc[i][4] + bv1.x; o1.y = acc[i][5] + bv1.y;
        o1.z = acc[i][6] + bv1.z; o1.w = acc[i][7] + bv1.w;
        if (ADD) {
            float4 r0 = *(const float4*)(C + off0);
            float4 r1 = *(const float4*)(C + off1);
            o0.x += r0.x; o0.y += r0.y; o0.z += r0.z; o0.w += r0.w;
            o1.x += r1.x; o1.y += r1.y; o1.z += r1.z; o1.w += r1.w;
        }
        *(float4*)(C + off0) = o0;
        *(float4*)(C + off1) = o1;
    }
}

template<bool ADD>
__global__ __launch_bounds__(256)
void gemm128(const float* __restrict__ A, const float* __restrict__ W,
             const float* __restrict__ bias, float* __restrict__ C,
             int N, int K, int lda)
{
    gemm128_body<ADD>(A, W, bias, C, N, K, lda, blockIdx.y * 128, blockIdx.x * 128);
}

// Fused Q/K/V projection: blockIdx.z selects the weight/bias/output triple.
__global__ __launch_bounds__(256)
void gemm128_qkv(const float* __restrict__ A,
                 const float* __restrict__ Wq, const float* __restrict__ Wk, const float* __restrict__ Wv,
                 const float* __restrict__ bq, const float* __restrict__ bk, const float* __restrict__ bv,
                 float* __restrict__ Cq, float* __restrict__ Ck, float* __restrict__ Cv)
{
    int z = blockIdx.z;
    const float* W = (z == 0) ? Wq : (z == 1) ? Wk : Wv;
    const float* b = (z == 0) ? bq : (z == 1) ? bk : bv;
    float*       C = (z == 0) ? Cq : (z == 1) ? Ck : Cv;
    gemm128_body<false>(A, W, b, C, HDIM, HDIM, HDIM, blockIdx.y * 128, blockIdx.x * 128);
}

// -------------------- fused attention (R3, verbatim) --------------------
__global__ __launch_bounds__(512, 1)
void attn_kernel(const float* __restrict__ Q, const float* __restrict__ Kt,
                 const float* __restrict__ V, const float* __restrict__ dist,
                 const unsigned int* __restrict__ mask,   // 4-byte elements; nonzero = masked
                 const float* __restrict__ demb,   // [50,8] for this layer
                 const float* __restrict__ abias,  // [8]    for this layer
                 float* __restrict__ out)
{
    extern __shared__ float sm[];
    float* Ksh = sm;                 // 512*17
    float* Vsh = Ksh + NN*KS;        // 512*17
    float* mb  = Vsh + NN*KS;        // 512
    float* de  = mb + NN;            // 64

    int b = blockIdx.x >> 3, h = blockIdx.x & 7;
    int tid = threadIdx.x;

    for (int idx = tid; idx < NN*4; idx += 512) {
        int r = idx >> 2, c = idx & 3;
        size_t goff = ((size_t)b*NN + r) * HDIM + h*HD + c*4;
        float4 kv = *(const float4*)(Kt + goff);
        Ksh[r*KS + c*4+0] = kv.x; Ksh[r*KS + c*4+1] = kv.y;
        Ksh[r*KS + c*4+2] = kv.z; Ksh[r*KS + c*4+3] = kv.w;
        float4 vv = *(const float4*)(V + goff);
        Vsh[r*KS + c*4+0] = vv.x; Vsh[r*KS + c*4+1] = vv.y;
        Vsh[r*KS + c*4+2] = vv.z; Vsh[r*KS + c*4+3] = vv.w;
    }
    if (tid < NN)  mb[tid] = (mask[(size_t)b*NN + tid] != 0u) ? -1e9f : 0.0f;
    if (tid < NUM_BINS) de[tid] = demb[tid*NHEADS + h];
    float ab = abias[h];
    __syncthreads();

    int warp = tid >> 5, lane = tid & 31;
    int qbase = blockIdx.y * 64 + warp * 4;

    for (int r = 0; r < 4; r++) {
        int q = qbase + r;
        const float* qp = Q + ((size_t)b*NN + q) * HDIM + h*HD;
        float qv[HD];
        #pragma unroll
        for (int d = 0; d < HD; d++) qv[d] = __ldg(qp + d);

        const float* drow = dist + ((size_t)b*NN + q) * NN;
        float sc[16];
        float mx = -3.4e38f;
        #pragma unroll
        for (int kk = 0; kk < 16; kk++) {
            int k = kk*32 + lane;
            float dv = drow[k];
            int bin = (int)(dv * 10.0f);
            bin = bin < 0 ? 0 : (bin > NUM_BINS-1 ? NUM_BINS-1 : bin);
            float dot = 0.0f;
            #pragma unroll
            for (int d = 0; d < HD; d++) dot = fmaf(qv[d], Ksh[k*KS + d], dot);
            float s = dot * 0.25f + de[bin] + ab + mb[k];
            sc[kk] = s;
            mx = fmaxf(mx, s);
        }
        #pragma unroll
        for (int o = 16; o > 0; o >>= 1)
            mx = fmaxf(mx, __shfl_xor_sync(0xffffffffu, mx, o));

        float ssum = 0.0f, acc[HD];
        #pragma unroll
        for (int d = 0; d < HD; d++) acc[d] = 0.0f;
        #pragma unroll
        for (int kk = 0; kk < 16; kk++) {
            int k = kk*32 + lane;
            float p = __expf(fmaxf(sc[kk] - mx, -80.0f));
            ssum += p;
            #pragma unroll
            for (int d = 0; d < HD; d++)
                acc[d] = fmaf(p, Vsh[k*KS + d], acc[d]);
        }
        #pragma unroll
        for (int o = 16; o > 0; o >>= 1) {
            ssum += __shfl_xor_sync(0xffffffffu, ssum, o);
            #pragma unroll
            for (int d = 0; d < HD; d++)
                acc[d] += __shfl_xor_sync(0xffffffffu, acc[d], o);
        }
        if (lane == 0) {
            float inv = 1.0f / ssum;
            float4* o4 = (float4*)(out + ((size_t)b*NN + q) * HDIM + h*HD);
            o4[0] = make_float4(acc[0]*inv,  acc[1]*inv,  acc[2]*inv,  acc[3]*inv);
            o4[1] = make_float4(acc[4]*inv,  acc[5]*inv,  acc[6]*inv,  acc[7]*inv);
            o4[2] = make_float4(acc[8]*inv,  acc[9]*inv,  acc[10]*inv, acc[11]*inv);
            o4[3] = make_float4(acc[12]*inv, acc[13]*inv, acc[14]*inv, acc[15]*inv);
        }
    }
}

// -------------------- GLU (R3, verbatim) --------------------
__global__ void glu_kernel(const float* __restrict__ u, float* __restrict__ g, int total4)
{
    int idx = blockIdx.x * blockDim.x + threadIdx.x;
    if (idx >= total4) return;
    int r = idx >> 7, j4 = idx & 127;
    float4 a = *(const float4*)(u + (size_t)r * (2*FF) + j4*4);
    float4 c = *(const float4*)(u + (size_t)r * (2*FF) + FF + j4*4);
    float4 o;
    o.x = a.x / (1.0f + __expf(-c.x));
    o.y = a.y / (1.0f + __expf(-c.y));
    o.z = a.z / (1.0f + __expf(-c.z));
    o.w = a.w / (1.0f + __expf(-c.w));
    *(float4*)(g + (size_t)r * FF + j4*4) = o;
}

// -------------------- launch --------------------
extern "C" void kernel_launch(void* const* d_in, const int* in_sizes, int n_in,
                              void* d_out, int out_size)
{
    const float*        x    = (const float*)d_in[0];
    const float*        dist = (const float*)d_in[1];
    const unsigned int* mask = (const unsigned int*)d_in[2];  // bool widened to 4-byte dtype
    const float* Wq  = (const float*)d_in[3];
    const float* bq  = (const float*)d_in[4];
    const float* Wk  = (const float*)d_in[5];
    const float* bk  = (const float*)d_in[6];
    const float* Wv  = (const float*)d_in[7];
    const float* bv  = (const float*)d_in[8];
    const float* Wo  = (const float*)d_in[9];
    const float* bo  = (const float*)d_in[10];
    const float* demb  = (const float*)d_in[11];
    const float* abias = (const float*)d_in[12];
    const float* g1  = (const float*)d_in[13];
    const float* b1  = (const float*)d_in[14];
    const float* g2  = (const float*)d_in[15];
    const float* b2  = (const float*)d_in[16];
    const float* Wf1 = (const float*)d_in[17];
    const float* bf1 = (const float*)d_in[18];
    const float* Wf2 = (const float*)d_in[19];
    const float* bf2 = (const float*)d_in[20];
    float* h = (float*)d_out;

    float *t0, *q, *k, *v, *a, *u, *g;
    cudaGetSymbolAddress((void**)&t0, g_t0);
    cudaGetSymbolAddress((void**)&q,  g_q);
    cudaGetSymbolAddress((void**)&k,  g_k);
    cudaGetSymbolAddress((void**)&v,  g_v);
    cudaGetSymbolAddress((void**)&a,  g_a);
    cudaGetSymbolAddress((void**)&u,  g_u);
    cudaGetSymbolAddress((void**)&g,  g_g);

    const int SMEM = (2*NN*KS + NN + 64) * (int)sizeof(float);
    cudaFuncSetAttribute(attn_kernel, cudaFuncAttributeMaxDynamicSharedMemorySize, SMEM);

    cudaMemcpyAsync(h, x, sizeof(float)*(size_t)ROWS*HDIM, cudaMemcpyDeviceToDevice, 0);

    for (int l = 0; l < LNUM; l++) {
        ln_kernel<<<ROWS/8, 256>>>(h, g1 + l*HDIM, b1 + l*HDIM, t0);

        // fused Q/K/V: grid.z selects projection (3 x 128 CTAs fills the chip)
        gemm128_qkv<<<dim3(1, ROWS/128, 3), 256>>>(t0,
            Wq + (size_t)l*HDIM*HDIM, Wk + (size_t)l*HDIM*HDIM, Wv + (size_t)l*HDIM*HDIM,
            bq + l*HDIM, bk + l*HDIM, bv + l*HDIM, q, k, v);

        attn_kernel<<<dim3(BSZ*NHEADS, NN/64), 512, SMEM>>>(q, k, v, dist, mask,
                                                            demb + l*NUM_BINS*NHEADS,
                                                            abias + l*NHEADS, a);

        gemm128<true><<<dim3(1, ROWS/128), 256>>>(a, Wo + (size_t)l*HDIM*HDIM, bo + l*HDIM, h, HDIM, HDIM, HDIM);

        ln_kernel<<<ROWS/8, 256>>>(h, g2 + l*HDIM, b2 + l*HDIM, t0);

        // FF1: t0[16384,128] @ Wf1[128,1024] -> u
        gemm128<false><<<dim3((2*FF)/128, ROWS/128), 256>>>(t0, Wf1 + (size_t)l*HDIM*2*FF, bf1 + l*2*FF, u, 2*FF, HDIM, HDIM);

        glu_kernel<<<(ROWS*FF/4 + 255)/256, 256>>>(u, g, ROWS*FF/4);

        // FF2: h += g[16384,512] @ Wf2[512,128] + bf2
        gemm128<true><<<dim3(1, ROWS/128), 256>>>(g, Wf2 + (size_t)l*FF*HDIM, bf2 + l*HDIM, h, HDIM, FF, FF);
    }
}